// round 11
// baseline (speedup 1.0000x reference)
#include <cuda_runtime.h>
#include <cuda_fp16.h>
#include <cstdint>

// ---------------------------------------------------------------------------
// StreamingMultiScaleTCN fused kernel, R11 (= R9/R10 resubmit; both hit infra
// failures and never ran). Per-branch templated fully unrolled conv stage
// (compile-time taps/dilation) so ptxas can software-pipeline weight LDGs
// and LDSM latency across taps.
//
// Branches: br0 K=3,d=1  br1 K=5,d=2  br2 K=9,d=4  br3 K=9,d=8 (zero taps
// skipped). relu(y+b), concat(128), 1x1 proj w_out + b_out.
// ---------------------------------------------------------------------------

#define XW 36    // xs row stride in words (72 halves); 36%32==4 -> conflict-free
#define AW 68    // act row stride in words (136 halves); 68%32==4

#define SMEM_WORDS (128 * AW)          // 8704 >= 192*XW=6912 (overlay ok)
#define SMEM_BYTES (SMEM_WORDS * 4)    // 34816 B

#define CONV_WORDS (4*9*4*32*8)   // [br][tap][ks4][lane][8w] = 36864
#define WO_WORDS   (4*8*32*8)     // [nq][ks8][lane][8w]      = 8192

__device__ __align__(16) uint32_t g_wfrag[CONV_WORDS];  // conv B-frags (half2)
__device__ __align__(16) uint32_t g_wofrag[WO_WORDS];   // w_out B-frags (half2)
__device__ float g_bcat[128];                           // concat branch biases

__device__ __forceinline__ uint32_t pack_h2(float a, float b) {
    __half2 h = __floats2half2_rn(a, b);
    return *reinterpret_cast<uint32_t*>(&h);
}

__device__ __forceinline__ void mma16(float* d, const uint32_t* a, const uint32_t* b) {
    asm volatile(
        "mma.sync.aligned.m16n8k16.row.col.f32.f16.f16.f32 "
        "{%0,%1,%2,%3}, {%4,%5,%6,%7}, {%8,%9}, {%0,%1,%2,%3};\n"
        : "+f"(d[0]), "+f"(d[1]), "+f"(d[2]), "+f"(d[3])
        : "r"(a[0]), "r"(a[1]), "r"(a[2]), "r"(a[3]),
          "r"(b[0]), "r"(b[1]));
}

__device__ __forceinline__ void ldsm4(uint32_t* r, uint32_t saddr) {
    asm volatile(
        "ldmatrix.sync.aligned.m8n8.x4.shared.b16 {%0,%1,%2,%3}, [%4];\n"
        : "=r"(r[0]), "=r"(r[1]), "=r"(r[2]), "=r"(r[3]) : "r"(saddr));
}

// --------------------------- weight prep kernel -----------------------------
// m16n8k16 col-major B fragment: thread(g=lane>>2, tg=lane&3) word w8 in [0,8):
//   nt = w8>>1, wlo = w8&1; k0 = ks*16 + 2*tg + 8*wlo; packs (k0, k0+1);
//   out col c = nt*8 + g.
__global__ void prep_kernel(const float* __restrict__ w_s, const float* __restrict__ w_m,
                            const float* __restrict__ w_l, const float* __restrict__ w_xl,
                            const float* __restrict__ b_s, const float* __restrict__ b_m,
                            const float* __restrict__ b_l, const float* __restrict__ b_xl,
                            const float* __restrict__ w_out) {
    int idx = blockIdx.x * 256 + threadIdx.x;
    if (idx < CONV_WORDS) {
        int w8   = idx & 7;
        int lane = (idx >> 3) & 31;
        int ks   = (idx >> 8) & 3;
        int bj   = idx >> 10;          // br*9 + j
        int j    = bj % 9;
        int br   = bj / 9;
        int tg = lane & 3, g = lane >> 2;
        int k0 = ks*16 + 2*tg + 8*(w8 & 1);
        int c  = (w8 >> 1)*8 + g;
        float v0 = 0.f, v1 = 0.f;
        if      (br == 0) { if (j >= 6) { v0 = w_s [((j-6)*64 + k0)*32 + c];
                                          v1 = w_s [((j-6)*64 + k0+1)*32 + c]; } }
        else if (br == 1) { if (j >= 4) { v0 = w_m [((j-4)*64 + k0)*32 + c];
                                          v1 = w_m [((j-4)*64 + k0+1)*32 + c]; } }
        else if (br == 2) {               v0 = w_l [(j*64 + k0)*32 + c];
                                          v1 = w_l [(j*64 + k0+1)*32 + c]; }
        else              {               v0 = w_xl[(j*64 + k0)*32 + c];
                                          v1 = w_xl[(j*64 + k0+1)*32 + c]; }
        g_wfrag[idx] = pack_h2(v0, v1);
    } else if (idx < CONV_WORDS + WO_WORDS) {
        int k2   = idx - CONV_WORDS;
        int w8   = k2 & 7;
        int lane = (k2 >> 3) & 31;
        int ks   = (k2 >> 8) & 7;
        int nq   = k2 >> 11;
        int tg = lane & 3, g = lane >> 2;
        int k0 = ks*16 + 2*tg + 8*(w8 & 1);
        int f  = nq*32 + (w8 >> 1)*8 + g;
        g_wofrag[k2] = pack_h2(w_out[k0*128 + f], w_out[(k0+1)*128 + f]);
    }
    if (blockIdx.x == 0 && threadIdx.x < 128) {
        int i = threadIdx.x;
        const float* bsel = (i < 32) ? b_s : (i < 64) ? b_m : (i < 96) ? b_l : b_xl;
        g_bcat[i] = bsel[i & 31];
    }
}

// --------------------- templated fully-unrolled conv ------------------------
template<int TAPS, int DIL, int JMIN>
__device__ __forceinline__ void conv_branch(
    float (&acc)[4][4][4], const uint4* __restrict__ wf_br,
    uint32_t smem_u32, int arowb, int lkw)
{
    #pragma unroll
    for (int jj = 0; jj < TAPS; jj++) {
        const int j   = JMIN + jj;
        const uint4* wf = wf_br + j*256;
        const int rb  = arowb - DIL * (8 - j);
        #pragma unroll
        for (int ks = 0; ks < 4; ks++) {
            uint4 bf0 = __ldg(wf + ks*64);
            uint4 bf1 = __ldg(wf + ks*64 + 1);
            uint32_t a[4][4];
            #pragma unroll
            for (int mt = 0; mt < 4; mt++) {
                uint32_t sa = smem_u32 + ((rb + mt*16)*XW + ks*8 + lkw) * 4;
                ldsm4(a[mt], sa);
            }
            uint32_t bw[8] = {bf0.x, bf0.y, bf0.z, bf0.w,
                              bf1.x, bf1.y, bf1.z, bf1.w};
            #pragma unroll
            for (int mt = 0; mt < 4; mt++)
                #pragma unroll
                for (int nt = 0; nt < 4; nt++)
                    mma16(acc[mt][nt], a[mt], bw + nt*2);
        }
    }
}

// ------------------------------ main kernel ---------------------------------
__global__ __launch_bounds__(256, 2)
void tcn_kernel(const float* __restrict__ x,
                const float* __restrict__ b_out, float* __restrict__ out) {
    extern __shared__ uint32_t smem[];   // xs [192][XW] then act [128][AW]

    const int tid  = threadIdx.x;
    const int lane = tid & 31;
    const int wrp  = tid >> 5;
    const int g    = lane >> 2;   // 0..7
    const int tg   = lane & 3;    // 0..3
    const int b    = blockIdx.y;
    const int t0   = blockIdx.x * 128;

    const uint32_t smem_u32 = (uint32_t)__cvta_generic_to_shared(smem);
    const int lrow = (lane & 7) + ((lane >> 3) & 1) * 8;  // ldmatrix row
    const int lkw  = (lane >> 4) * 4;                     // k-half word off

    // ---- Stage A: x tile (64-row causal halo) -> smem, fp16 ----
    {
        const float* xb = x + ((size_t)b * 8192) * 64;
        #pragma unroll 4
        for (int i = tid; i < 192*16; i += 256) {
            int r = i >> 4, q = i & 15;
            int gt = t0 - 64 + r;
            float4 v = make_float4(0.f, 0.f, 0.f, 0.f);
            if (gt >= 0) v = *(const float4*)(xb + (size_t)gt*64 + q*4);
            uint2 h = make_uint2(pack_h2(v.x, v.y), pack_h2(v.z, v.w));
            *(uint2*)(smem + r*XW + q*2) = h;
        }
    }
    __syncthreads();

    const int br    = wrp >> 1;     // branch (warp-uniform)
    const int thalf = wrp & 1;      // t half

    float acc[4][4][4];
    #pragma unroll
    for (int mt = 0; mt < 4; mt++)
        #pragma unroll
        for (int nt = 0; nt < 4; nt++)
            #pragma unroll
            for (int r = 0; r < 4; r++) acc[mt][nt][r] = 0.f;

    // ---- Stage B: per-branch fully-unrolled conv GEMMs ----
    {
        const uint4* wf_br = (const uint4*)g_wfrag + (size_t)br*9*256 + lane*2;
        const int arowb = 64 + thalf*64 + lrow;
        switch (br) {
            case 0: conv_branch<3, 1, 6>(acc, wf_br, smem_u32, arowb, lkw); break;
            case 1: conv_branch<5, 2, 4>(acc, wf_br, smem_u32, arowb, lkw); break;
            case 2: conv_branch<9, 4, 0>(acc, wf_br, smem_u32, arowb, lkw); break;
            default: conv_branch<9, 8, 0>(acc, wf_br, smem_u32, arowb, lkw); break;
        }
    }
    __syncthreads();   // all warps done reading xs before act overlays it

    // ---- bias + relu -> act smem (fp16) ----
    {
        #pragma unroll
        for (int nt = 0; nt < 4; nt++) {
            int c = br*32 + nt*8 + 2*tg;
            float2 bv = *(const float2*)(g_bcat + c);
            int cw = (c >> 1);
            #pragma unroll
            for (int mt = 0; mt < 4; mt++) {
                int r0 = thalf*64 + mt*16 + g;
                float v0 = fmaxf(acc[mt][nt][0] + bv.x, 0.f);
                float v1 = fmaxf(acc[mt][nt][1] + bv.y, 0.f);
                float v2 = fmaxf(acc[mt][nt][2] + bv.x, 0.f);
                float v3 = fmaxf(acc[mt][nt][3] + bv.y, 0.f);
                smem[r0*AW + cw]     = pack_h2(v0, v1);
                smem[(r0+8)*AW + cw] = pack_h2(v2, v3);
            }
        }
    }
    __syncthreads();

    // ---- Stage C: out = relu_act @ w_out + b_out (128x128x128) ----
    const int mq = wrp >> 2;   // t half
    const int nq = wrp & 3;    // f quarter
    #pragma unroll
    for (int mt = 0; mt < 4; mt++)
        #pragma unroll
        for (int nt = 0; nt < 4; nt++)
            #pragma unroll
            for (int r = 0; r < 4; r++) acc[mt][nt][r] = 0.f;

    {
        const uint4* wof = (const uint4*)g_wofrag + (size_t)nq*512 + lane*2;
        const int crowb = mq*64 + lrow;
        #pragma unroll
        for (int ks = 0; ks < 8; ks++) {
            uint4 bf0 = __ldg(wof + ks*64);
            uint4 bf1 = __ldg(wof + ks*64 + 1);
            uint32_t a[4][4];
            #pragma unroll
            for (int mt = 0; mt < 4; mt++) {
                uint32_t sa = smem_u32 + ((crowb + mt*16)*AW + ks*8 + lkw) * 4;
                ldsm4(a[mt], sa);
            }
            uint32_t bw[8] = {bf0.x, bf0.y, bf0.z, bf0.w,
                              bf1.x, bf1.y, bf1.z, bf1.w};
            #pragma unroll
            for (int mt = 0; mt < 4; mt++)
                #pragma unroll
                for (int nt = 0; nt < 4; nt++)
                    mma16(acc[mt][nt], a[mt], bw + nt*2);
        }
    }

    // ---- epilogue: + b_out, store fp32 ----
    {
        float* ob = out + ((size_t)b*8192 + t0) * 128;
        #pragma unroll
        for (int nt = 0; nt < 4; nt++) {
            int c = nq*32 + nt*8 + 2*tg;
            float2 bv = *(const float2*)(b_out + c);
            #pragma unroll
            for (int mt = 0; mt < 4; mt++) {
                int r0 = mq*64 + mt*16 + g;
                *(float2*)(ob + (size_t)r0*128 + c) =
                    make_float2(acc[mt][nt][0] + bv.x, acc[mt][nt][1] + bv.y);
                *(float2*)(ob + (size_t)(r0+8)*128 + c) =
                    make_float2(acc[mt][nt][2] + bv.x, acc[mt][nt][3] + bv.y);
            }
        }
    }
}

// ------------------------------ launcher ------------------------------------
extern "C" void kernel_launch(void* const* d_in, const int* in_sizes, int n_in,
                              void* d_out, int out_size) {
    const float* x     = (const float*)d_in[0];
    const float* w_s   = (const float*)d_in[1];
    const float* b_s   = (const float*)d_in[2];
    const float* w_m   = (const float*)d_in[3];
    const float* b_m   = (const float*)d_in[4];
    const float* w_l   = (const float*)d_in[5];
    const float* b_l   = (const float*)d_in[6];
    const float* w_xl  = (const float*)d_in[7];
    const float* b_xl  = (const float*)d_in[8];
    const float* w_out = (const float*)d_in[9];
    const float* b_out = (const float*)d_in[10];
    float* out = (float*)d_out;

    cudaFuncSetAttribute(tcn_kernel, cudaFuncAttributeMaxDynamicSharedMemorySize, SMEM_BYTES);

    prep_kernel<<<(CONV_WORDS + WO_WORDS + 255)/256, 256>>>(
        w_s, w_m, w_l, w_xl, b_s, b_m, b_l, b_xl, w_out);

    dim3 grid(8192 / 128, 16);   // (t-tiles, batch)
    tcn_kernel<<<grid, 256, SMEM_BYTES>>>(x, b_out, out);
}

// round 15
// speedup vs baseline: 1.1635x; 1.1635x over previous
#include <cuda_runtime.h>
#include <cuda_fp16.h>
#include <cstdint>

// ---------------------------------------------------------------------------
// StreamingMultiScaleTCN fused kernel, R15: back to the proven mma.sync
// family (tcgen05 is unavailable: harness compiles for sm_100, not sm_100a).
// R8 structure with 64-timestep CTA tiles -> acc regs halved -> 3 CTAs/SM
// (24 warps/SM) for latency cover.
//
// Branches: br0 K=3,d=1  br1 K=5,d=2  br2 K=9,d=4  br3 K=9,d=8 (zero taps
// skipped). relu(y+b), concat(128), 1x1 proj w_out + b_out.
//
// Per CTA (256 thr, 8 warps): one batch b, 64 timesteps.
//   A: x[t0-64..t0+64) x 64ch -> smem fp16               [syncthreads]
//   B: warp=(branch,thalf32): conv GEMMs m16n8k16, warp tile 32t x 32c;
//      A via ldmatrix.x4, B via fragment-packed LDG.128   [syncthreads]
//   relu+bias -> act smem fp16 (overlays xs)              [syncthreads]
//   C: warp=(mq,nq): out = act @ w_out + b_out, 32t x 32f tiles
// ---------------------------------------------------------------------------

#define XW 36    // xs row stride in words (72 halves); 36%32==4 -> conflict-free
#define AW 68    // act row stride in words (136 halves); 68%32==4

#define SMEM_WORDS (128 * XW)          // 4608 >= 64*AW=4352 (overlay ok)
#define SMEM_BYTES (SMEM_WORDS * 4)    // 18432 B -> 3 CTAs/SM trivially

#define CONV_WORDS (4*9*4*32*8)   // [br][tap][ks4][lane][8w] = 36864
#define WO_WORDS   (4*8*32*8)     // [nq][ks8][lane][8w]      = 8192

__device__ __align__(16) uint32_t g_wfrag[CONV_WORDS];  // conv B-frags (half2)
__device__ __align__(16) uint32_t g_wofrag[WO_WORDS];   // w_out B-frags (half2)
__device__ float g_bcat[128];                           // concat branch biases

__device__ __forceinline__ uint32_t pack_h2(float a, float b) {
    __half2 h = __floats2half2_rn(a, b);
    return *reinterpret_cast<uint32_t*>(&h);
}

__device__ __forceinline__ void mma16(float* d, const uint32_t* a, const uint32_t* b) {
    asm volatile(
        "mma.sync.aligned.m16n8k16.row.col.f32.f16.f16.f32 "
        "{%0,%1,%2,%3}, {%4,%5,%6,%7}, {%8,%9}, {%0,%1,%2,%3};\n"
        : "+f"(d[0]), "+f"(d[1]), "+f"(d[2]), "+f"(d[3])
        : "r"(a[0]), "r"(a[1]), "r"(a[2]), "r"(a[3]),
          "r"(b[0]), "r"(b[1]));
}

__device__ __forceinline__ void ldsm4(uint32_t* r, uint32_t saddr) {
    asm volatile(
        "ldmatrix.sync.aligned.m8n8.x4.shared.b16 {%0,%1,%2,%3}, [%4];\n"
        : "=r"(r[0]), "=r"(r[1]), "=r"(r[2]), "=r"(r[3]) : "r"(saddr));
}

// --------------------------- weight prep kernel -----------------------------
// m16n8k16 col-major B fragment: thread(g=lane>>2, tg=lane&3) word w8 in [0,8):
//   nt = w8>>1, wlo = w8&1; k0 = ks*16 + 2*tg + 8*wlo; packs (k0, k0+1);
//   out col c = nt*8 + g.
__global__ void prep_kernel(const float* __restrict__ w_s, const float* __restrict__ w_m,
                            const float* __restrict__ w_l, const float* __restrict__ w_xl,
                            const float* __restrict__ b_s, const float* __restrict__ b_m,
                            const float* __restrict__ b_l, const float* __restrict__ b_xl,
                            const float* __restrict__ w_out) {
    int idx = blockIdx.x * 256 + threadIdx.x;
    if (idx < CONV_WORDS) {
        int w8   = idx & 7;
        int lane = (idx >> 3) & 31;
        int ks   = (idx >> 8) & 3;
        int bj   = idx >> 10;          // br*9 + j
        int j    = bj % 9;
        int br   = bj / 9;
        int tg = lane & 3, g = lane >> 2;
        int k0 = ks*16 + 2*tg + 8*(w8 & 1);
        int c  = (w8 >> 1)*8 + g;
        float v0 = 0.f, v1 = 0.f;
        if      (br == 0) { if (j >= 6) { v0 = w_s [((j-6)*64 + k0)*32 + c];
                                          v1 = w_s [((j-6)*64 + k0+1)*32 + c]; } }
        else if (br == 1) { if (j >= 4) { v0 = w_m [((j-4)*64 + k0)*32 + c];
                                          v1 = w_m [((j-4)*64 + k0+1)*32 + c]; } }
        else if (br == 2) {               v0 = w_l [(j*64 + k0)*32 + c];
                                          v1 = w_l [(j*64 + k0+1)*32 + c]; }
        else              {               v0 = w_xl[(j*64 + k0)*32 + c];
                                          v1 = w_xl[(j*64 + k0+1)*32 + c]; }
        g_wfrag[idx] = pack_h2(v0, v1);
    } else if (idx < CONV_WORDS + WO_WORDS) {
        int k2   = idx - CONV_WORDS;
        int w8   = k2 & 7;
        int lane = (k2 >> 3) & 31;
        int ks   = (k2 >> 8) & 7;
        int nq   = k2 >> 11;
        int tg = lane & 3, g = lane >> 2;
        int k0 = ks*16 + 2*tg + 8*(w8 & 1);
        int f  = nq*32 + (w8 >> 1)*8 + g;
        g_wofrag[k2] = pack_h2(w_out[k0*128 + f], w_out[(k0+1)*128 + f]);
    }
    if (blockIdx.x == 0 && threadIdx.x < 128) {
        int i = threadIdx.x;
        const float* bsel = (i < 32) ? b_s : (i < 64) ? b_m : (i < 96) ? b_l : b_xl;
        g_bcat[i] = bsel[i & 31];
    }
}

// ------------------------------ main kernel ---------------------------------
__global__ __launch_bounds__(256, 3)
void tcn_kernel(const float* __restrict__ x,
                const float* __restrict__ b_out, float* __restrict__ out) {
    extern __shared__ uint32_t smem[];   // xs [128][XW] then act [64][AW]

    const int tid  = threadIdx.x;
    const int lane = tid & 31;
    const int wrp  = tid >> 5;
    const int g    = lane >> 2;   // 0..7
    const int tg   = lane & 3;    // 0..3
    const int b    = blockIdx.y;
    const int t0   = blockIdx.x * 64;

    const uint32_t smem_u32 = (uint32_t)__cvta_generic_to_shared(smem);
    const int lrow = (lane & 7) + ((lane >> 3) & 1) * 8;  // ldmatrix row
    const int lkw  = (lane >> 4) * 4;                     // k-half word off

    // ---- Stage A: x tile (64-row causal halo + 64 rows) -> smem, fp16 ----
    {
        const float* xb = x + ((size_t)b * 8192) * 64;
        #pragma unroll 4
        for (int i = tid; i < 128*16; i += 256) {
            int r = i >> 4, q = i & 15;
            int gt = t0 - 64 + r;
            float4 v = make_float4(0.f, 0.f, 0.f, 0.f);
            if (gt >= 0) v = *(const float4*)(xb + (size_t)gt*64 + q*4);
            uint2 h = make_uint2(pack_h2(v.x, v.y), pack_h2(v.z, v.w));
            *(uint2*)(smem + r*XW + q*2) = h;
        }
    }
    __syncthreads();

    const int br    = wrp >> 1;     // branch (warp-uniform)
    const int thalf = wrp & 1;      // 32-t half
    const int dil   = 1 << br;      // 1,2,4,8
    const int jmin  = (br == 0) ? 6 : (br == 1) ? 4 : 0;

    float acc[2][4][4];
    #pragma unroll
    for (int mt = 0; mt < 2; mt++)
        #pragma unroll
        for (int nt = 0; nt < 4; nt++)
            #pragma unroll
            for (int r = 0; r < 4; r++) acc[mt][nt][r] = 0.f;

    // ---- Stage B: per-warp conv GEMMs (m16n8k16), 32t x 32c warp tile ----
    {
        const uint4* wf_br = (const uint4*)g_wfrag + (size_t)br*9*256 + lane*2;
        for (int j = jmin; j < 9; j++) {
            const uint4* wf = wf_br + j*256;
            const int off   = dil * (8 - j);
            const int arowb = 64 + thalf*32 - off + lrow;

            #pragma unroll
            for (int ks = 0; ks < 4; ks++) {
                uint4 bf0 = __ldg(wf + ks*64);
                uint4 bf1 = __ldg(wf + ks*64 + 1);
                uint32_t a[2][4];
                #pragma unroll
                for (int mt = 0; mt < 2; mt++) {
                    uint32_t sa = smem_u32 +
                        ((arowb + mt*16)*XW + ks*8 + lkw) * 4;
                    ldsm4(a[mt], sa);
                }
                uint32_t bw[8] = {bf0.x, bf0.y, bf0.z, bf0.w,
                                  bf1.x, bf1.y, bf1.z, bf1.w};
                #pragma unroll
                for (int mt = 0; mt < 2; mt++)
                    #pragma unroll
                    for (int nt = 0; nt < 4; nt++)
                        mma16(acc[mt][nt], a[mt], bw + nt*2);
            }
        }
    }
    __syncthreads();   // all warps done reading xs before act overlays it

    // ---- bias + relu -> act smem (fp16) ----
    {
        #pragma unroll
        for (int nt = 0; nt < 4; nt++) {
            int c = br*32 + nt*8 + 2*tg;              // even channel
            float2 bv = *(const float2*)(g_bcat + c);
            int cw = (c >> 1);                        // half2 word col
            #pragma unroll
            for (int mt = 0; mt < 2; mt++) {
                int r0 = thalf*32 + mt*16 + g;
                float v0 = fmaxf(acc[mt][nt][0] + bv.x, 0.f);
                float v1 = fmaxf(acc[mt][nt][1] + bv.y, 0.f);
                float v2 = fmaxf(acc[mt][nt][2] + bv.x, 0.f);
                float v3 = fmaxf(acc[mt][nt][3] + bv.y, 0.f);
                smem[r0*AW + cw]     = pack_h2(v0, v1);
                smem[(r0+8)*AW + cw] = pack_h2(v2, v3);
            }
        }
    }
    __syncthreads();

    // ---- Stage C: out = relu_act @ w_out + b_out (64x128x128) ----
    const int mq = wrp >> 2;   // 32-t half
    const int nq = wrp & 3;    // f quarter
    #pragma unroll
    for (int mt = 0; mt < 2; mt++)
        #pragma unroll
        for (int nt = 0; nt < 4; nt++)
            #pragma unroll
            for (int r = 0; r < 4; r++) acc[mt][nt][r] = 0.f;

    {
        const uint4* wof = (const uint4*)g_wofrag + (size_t)nq*512 + lane*2;
        const int crowb = mq*32 + lrow;
        #pragma unroll
        for (int ks = 0; ks < 8; ks++) {
            uint4 bf0 = __ldg(wof + ks*64);
            uint4 bf1 = __ldg(wof + ks*64 + 1);
            uint32_t a[2][4];
            #pragma unroll
            for (int mt = 0; mt < 2; mt++) {
                uint32_t sa = smem_u32 +
                    ((crowb + mt*16)*AW + ks*8 + lkw) * 4;
                ldsm4(a[mt], sa);
            }
            uint32_t bw[8] = {bf0.x, bf0.y, bf0.z, bf0.w,
                              bf1.x, bf1.y, bf1.z, bf1.w};
            #pragma unroll
            for (int mt = 0; mt < 2; mt++)
                #pragma unroll
                for (int nt = 0; nt < 4; nt++)
                    mma16(acc[mt][nt], a[mt], bw + nt*2);
        }
    }

    // ---- epilogue: + b_out, store fp32 ----
    {
        float* ob = out + ((size_t)b*8192 + t0) * 128;
        #pragma unroll
        for (int nt = 0; nt < 4; nt++) {
            int c = nq*32 + nt*8 + 2*tg;
            float2 bv = *(const float2*)(b_out + c);
            #pragma unroll
            for (int mt = 0; mt < 2; mt++) {
                int r0 = mq*32 + mt*16 + g;
                *(float2*)(ob + (size_t)r0*128 + c) =
                    make_float2(acc[mt][nt][0] + bv.x, acc[mt][nt][1] + bv.y);
                *(float2*)(ob + (size_t)(r0+8)*128 + c) =
                    make_float2(acc[mt][nt][2] + bv.x, acc[mt][nt][3] + bv.y);
            }
        }
    }
}

// ------------------------------ launcher ------------------------------------
extern "C" void kernel_launch(void* const* d_in, const int* in_sizes, int n_in,
                              void* d_out, int out_size) {
    const float* x     = (const float*)d_in[0];
    const float* w_s   = (const float*)d_in[1];
    const float* b_s   = (const float*)d_in[2];
    const float* w_m   = (const float*)d_in[3];
    const float* b_m   = (const float*)d_in[4];
    const float* w_l   = (const float*)d_in[5];
    const float* b_l   = (const float*)d_in[6];
    const float* w_xl  = (const float*)d_in[7];
    const float* b_xl  = (const float*)d_in[8];
    const float* w_out = (const float*)d_in[9];
    const float* b_out = (const float*)d_in[10];
    float* out = (float*)d_out;

    cudaFuncSetAttribute(tcn_kernel, cudaFuncAttributeMaxDynamicSharedMemorySize, SMEM_BYTES);

    prep_kernel<<<(CONV_WORDS + WO_WORDS + 255)/256, 256>>>(
        w_s, w_m, w_l, w_xl, b_s, b_m, b_l, b_xl, w_out);

    dim3 grid(8192 / 64, 16);   // (t-tiles, batch)
    tcn_kernel<<<grid, 256, SMEM_BYTES>>>(x, b_out, out);
}

// round 16
// speedup vs baseline: 1.5101x; 1.2979x over previous
#include <cuda_runtime.h>
#include <cuda_fp16.h>
#include <cstdint>

// ---------------------------------------------------------------------------
// StreamingMultiScaleTCN fused kernel, R16: exact R8 structure (measured
// 69.6us; best) + depth-1 software pipeline on B fragments: prefetch next
// (ks | tap) weight LDGs during the current MMA burst, in conv and proj.
//
// Branches: br0 K=3,d=1  br1 K=5,d=2  br2 K=9,d=4  br3 K=9,d=8 (zero taps
// skipped). relu(y+b), concat(128), 1x1 proj w_out + b_out.
//
// Per CTA (256 thr, 8 warps, 2 CTAs/SM): one batch b, 128 timesteps.
//   A: x[t0-64..t0+128) x 64ch -> smem fp16              [syncthreads]
//   B: warp=(branch,thalf): conv GEMMs m16n8k16, 64t x 32c warp tile;
//      A via ldmatrix.x4, B via pipelined fragment LDG.128 [syncthreads]
//   relu+bias -> act smem fp16 (overlays xs)              [syncthreads]
//   C: warp=(mq,nq): out = act @ w_out + b_out, pipelined B
// ---------------------------------------------------------------------------

#define XW 36    // xs row stride in words (72 halves); 36%32==4 -> conflict-free
#define AW 68    // act row stride in words (136 halves); 68%32==4

#define SMEM_WORDS (128 * AW)          // 8704 >= 192*XW=6912 (overlay ok)
#define SMEM_BYTES (SMEM_WORDS * 4)    // 34816 B -> 2 CTAs/SM

#define CONV_WORDS (4*9*4*32*8)   // [br][tap][ks4][lane][8w] = 36864
#define WO_WORDS   (4*8*32*8)     // [nq][ks8][lane][8w]      = 8192

__device__ __align__(16) uint32_t g_wfrag[CONV_WORDS];  // conv B-frags (half2)
__device__ __align__(16) uint32_t g_wofrag[WO_WORDS];   // w_out B-frags (half2)
__device__ float g_bcat[128];                           // concat branch biases

__device__ __forceinline__ uint32_t pack_h2(float a, float b) {
    __half2 h = __floats2half2_rn(a, b);
    return *reinterpret_cast<uint32_t*>(&h);
}

__device__ __forceinline__ void mma16(float* d, const uint32_t* a, const uint32_t* b) {
    asm volatile(
        "mma.sync.aligned.m16n8k16.row.col.f32.f16.f16.f32 "
        "{%0,%1,%2,%3}, {%4,%5,%6,%7}, {%8,%9}, {%0,%1,%2,%3};\n"
        : "+f"(d[0]), "+f"(d[1]), "+f"(d[2]), "+f"(d[3])
        : "r"(a[0]), "r"(a[1]), "r"(a[2]), "r"(a[3]),
          "r"(b[0]), "r"(b[1]));
}

__device__ __forceinline__ void ldsm4(uint32_t* r, uint32_t saddr) {
    asm volatile(
        "ldmatrix.sync.aligned.m8n8.x4.shared.b16 {%0,%1,%2,%3}, [%4];\n"
        : "=r"(r[0]), "=r"(r[1]), "=r"(r[2]), "=r"(r[3]) : "r"(saddr));
}

// --------------------------- weight prep kernel -----------------------------
// m16n8k16 col-major B fragment: thread(g=lane>>2, tg=lane&3) word w8 in [0,8):
//   nt = w8>>1, wlo = w8&1; k0 = ks*16 + 2*tg + 8*wlo; packs (k0, k0+1);
//   out col c = nt*8 + g.
__global__ void prep_kernel(const float* __restrict__ w_s, const float* __restrict__ w_m,
                            const float* __restrict__ w_l, const float* __restrict__ w_xl,
                            const float* __restrict__ b_s, const float* __restrict__ b_m,
                            const float* __restrict__ b_l, const float* __restrict__ b_xl,
                            const float* __restrict__ w_out) {
    int idx = blockIdx.x * 256 + threadIdx.x;
    if (idx < CONV_WORDS) {
        int w8   = idx & 7;
        int lane = (idx >> 3) & 31;
        int ks   = (idx >> 8) & 3;
        int bj   = idx >> 10;          // br*9 + j
        int j    = bj % 9;
        int br   = bj / 9;
        int tg = lane & 3, g = lane >> 2;
        int k0 = ks*16 + 2*tg + 8*(w8 & 1);
        int c  = (w8 >> 1)*8 + g;
        float v0 = 0.f, v1 = 0.f;
        if      (br == 0) { if (j >= 6) { v0 = w_s [((j-6)*64 + k0)*32 + c];
                                          v1 = w_s [((j-6)*64 + k0+1)*32 + c]; } }
        else if (br == 1) { if (j >= 4) { v0 = w_m [((j-4)*64 + k0)*32 + c];
                                          v1 = w_m [((j-4)*64 + k0+1)*32 + c]; } }
        else if (br == 2) {               v0 = w_l [(j*64 + k0)*32 + c];
                                          v1 = w_l [(j*64 + k0+1)*32 + c]; }
        else              {               v0 = w_xl[(j*64 + k0)*32 + c];
                                          v1 = w_xl[(j*64 + k0+1)*32 + c]; }
        g_wfrag[idx] = pack_h2(v0, v1);
    } else if (idx < CONV_WORDS + WO_WORDS) {
        int k2   = idx - CONV_WORDS;
        int w8   = k2 & 7;
        int lane = (k2 >> 3) & 31;
        int ks   = (k2 >> 8) & 7;
        int nq   = k2 >> 11;
        int tg = lane & 3, g = lane >> 2;
        int k0 = ks*16 + 2*tg + 8*(w8 & 1);
        int f  = nq*32 + (w8 >> 1)*8 + g;
        g_wofrag[k2] = pack_h2(w_out[k0*128 + f], w_out[(k0+1)*128 + f]);
    }
    if (blockIdx.x == 0 && threadIdx.x < 128) {
        int i = threadIdx.x;
        const float* bsel = (i < 32) ? b_s : (i < 64) ? b_m : (i < 96) ? b_l : b_xl;
        g_bcat[i] = bsel[i & 31];
    }
}

// ------------------------------ main kernel ---------------------------------
__global__ __launch_bounds__(256, 2)
void tcn_kernel(const float* __restrict__ x,
                const float* __restrict__ b_out, float* __restrict__ out) {
    extern __shared__ uint32_t smem[];   // xs [192][XW] then act [128][AW]

    const int tid  = threadIdx.x;
    const int lane = tid & 31;
    const int wrp  = tid >> 5;
    const int g    = lane >> 2;   // 0..7
    const int tg   = lane & 3;    // 0..3
    const int b    = blockIdx.y;
    const int t0   = blockIdx.x * 128;

    const uint32_t smem_u32 = (uint32_t)__cvta_generic_to_shared(smem);
    const int lrow = (lane & 7) + ((lane >> 3) & 1) * 8;  // ldmatrix row
    const int lkw  = (lane >> 4) * 4;                     // k-half word off

    // ---- Stage A: x tile (64-row causal halo) -> smem, fp16 ----
    {
        const float* xb = x + ((size_t)b * 8192) * 64;
        #pragma unroll 4
        for (int i = tid; i < 192*16; i += 256) {
            int r = i >> 4, q = i & 15;
            int gt = t0 - 64 + r;
            float4 v = make_float4(0.f, 0.f, 0.f, 0.f);
            if (gt >= 0) v = *(const float4*)(xb + (size_t)gt*64 + q*4);
            uint2 h = make_uint2(pack_h2(v.x, v.y), pack_h2(v.z, v.w));
            *(uint2*)(smem + r*XW + q*2) = h;
        }
    }
    __syncthreads();

    const int br    = wrp >> 1;     // branch (warp-uniform)
    const int thalf = wrp & 1;      // t half
    const int dil   = 1 << br;      // 1,2,4,8
    const int jmin  = (br == 0) ? 6 : (br == 1) ? 4 : 0;

    float acc[4][4][4];
    #pragma unroll
    for (int mt = 0; mt < 4; mt++)
        #pragma unroll
        for (int nt = 0; nt < 4; nt++)
            #pragma unroll
            for (int r = 0; r < 4; r++) acc[mt][nt][r] = 0.f;

    // ---- Stage B: per-warp conv GEMMs (m16n8k16), pipelined B LDG ----
    {
        const uint4* wf_br = (const uint4*)g_wfrag + (size_t)br*9*256 + lane*2;
        uint4 nb0, nb1;
        {   // prime the pipe with tap jmin, ks 0
            const uint4* w0 = wf_br + jmin*256;
            nb0 = __ldg(w0); nb1 = __ldg(w0 + 1);
        }
        for (int j = jmin; j < 9; j++) {
            const int off   = dil * (8 - j);
            const int arowb = 64 + thalf*64 - off + lrow;

            #pragma unroll
            for (int ks = 0; ks < 4; ks++) {
                uint4 b0 = nb0, b1 = nb1;
                // prefetch next B: ks+1 of this tap, or ks0 of the next tap
                const uint4* nwf = (ks < 3)
                    ? (wf_br + j*256 + (ks+1)*64)
                    : (wf_br + ((j < 8) ? (j+1) : 8)*256);
                nb0 = __ldg(nwf); nb1 = __ldg(nwf + 1);

                uint32_t a[4][4];
                #pragma unroll
                for (int mt = 0; mt < 4; mt++) {
                    uint32_t sa = smem_u32 +
                        ((arowb + mt*16)*XW + ks*8 + lkw) * 4;
                    ldsm4(a[mt], sa);
                }
                uint32_t bw[8] = {b0.x, b0.y, b0.z, b0.w,
                                  b1.x, b1.y, b1.z, b1.w};
                #pragma unroll
                for (int mt = 0; mt < 4; mt++)
                    #pragma unroll
                    for (int nt = 0; nt < 4; nt++)
                        mma16(acc[mt][nt], a[mt], bw + nt*2);
            }
        }
    }
    __syncthreads();   // all warps done reading xs before act overlays it

    // ---- bias + relu -> act smem (fp16) ----
    {
        #pragma unroll
        for (int nt = 0; nt < 4; nt++) {
            int c = br*32 + nt*8 + 2*tg;              // even channel
            float2 bv = *(const float2*)(g_bcat + c);
            int cw = (c >> 1);                        // half2 word col
            #pragma unroll
            for (int mt = 0; mt < 4; mt++) {
                int r0 = thalf*64 + mt*16 + g;
                float v0 = fmaxf(acc[mt][nt][0] + bv.x, 0.f);
                float v1 = fmaxf(acc[mt][nt][1] + bv.y, 0.f);
                float v2 = fmaxf(acc[mt][nt][2] + bv.x, 0.f);
                float v3 = fmaxf(acc[mt][nt][3] + bv.y, 0.f);
                smem[r0*AW + cw]     = pack_h2(v0, v1);
                smem[(r0+8)*AW + cw] = pack_h2(v2, v3);
            }
        }
    }
    __syncthreads();

    // ---- Stage C: out = relu_act @ w_out + b_out (128x128x128) ----
    const int mq = wrp >> 2;   // t half
    const int nq = wrp & 3;    // f quarter
    #pragma unroll
    for (int mt = 0; mt < 4; mt++)
        #pragma unroll
        for (int nt = 0; nt < 4; nt++)
            #pragma unroll
            for (int r = 0; r < 4; r++) acc[mt][nt][r] = 0.f;

    {
        const uint4* wof = (const uint4*)g_wofrag + (size_t)nq*512 + lane*2;
        const int crowb = mq*64 + lrow;
        uint4 nb0 = __ldg(wof), nb1 = __ldg(wof + 1);
        #pragma unroll
        for (int ks = 0; ks < 8; ks++) {
            uint4 b0 = nb0, b1 = nb1;
            const uint4* nwf = wof + ((ks < 7) ? (ks+1) : 7)*64;
            nb0 = __ldg(nwf); nb1 = __ldg(nwf + 1);

            uint32_t a[4][4];
            #pragma unroll
            for (int mt = 0; mt < 4; mt++) {
                uint32_t sa = smem_u32 +
                    ((crowb + mt*16)*AW + ks*8 + lkw) * 4;
                ldsm4(a[mt], sa);
            }
            uint32_t bw[8] = {b0.x, b0.y, b0.z, b0.w,
                              b1.x, b1.y, b1.z, b1.w};
            #pragma unroll
            for (int mt = 0; mt < 4; mt++)
                #pragma unroll
                for (int nt = 0; nt < 4; nt++)
                    mma16(acc[mt][nt], a[mt], bw + nt*2);
        }
    }

    // ---- epilogue: + b_out, store fp32 ----
    {
        float* ob = out + ((size_t)b*8192 + t0) * 128;
        #pragma unroll
        for (int nt = 0; nt < 4; nt++) {
            int c = nq*32 + nt*8 + 2*tg;
            float2 bv = *(const float2*)(b_out + c);
            #pragma unroll
            for (int mt = 0; mt < 4; mt++) {
                int r0 = mq*64 + mt*16 + g;
                *(float2*)(ob + (size_t)r0*128 + c) =
                    make_float2(acc[mt][nt][0] + bv.x, acc[mt][nt][1] + bv.y);
                *(float2*)(ob + (size_t)(r0+8)*128 + c) =
                    make_float2(acc[mt][nt][2] + bv.x, acc[mt][nt][3] + bv.y);
            }
        }
    }
}

// ------------------------------ launcher ------------------------------------
extern "C" void kernel_launch(void* const* d_in, const int* in_sizes, int n_in,
                              void* d_out, int out_size) {
    const float* x     = (const float*)d_in[0];
    const float* w_s   = (const float*)d_in[1];
    const float* b_s   = (const float*)d_in[2];
    const float* w_m   = (const float*)d_in[3];
    const float* b_m   = (const float*)d_in[4];
    const float* w_l   = (const float*)d_in[5];
    const float* b_l   = (const float*)d_in[6];
    const float* w_xl  = (const float*)d_in[7];
    const float* b_xl  = (const float*)d_in[8];
    const float* w_out = (const float*)d_in[9];
    const float* b_out = (const float*)d_in[10];
    float* out = (float*)d_out;

    cudaFuncSetAttribute(tcn_kernel, cudaFuncAttributeMaxDynamicSharedMemorySize, SMEM_BYTES);

    prep_kernel<<<(CONV_WORDS + WO_WORDS + 255)/256, 256>>>(
        w_s, w_m, w_l, w_xl, b_s, b_m, b_l, b_xl, w_out);

    dim3 grid(8192 / 128, 16);   // (t-tiles, batch)
    tcn_kernel<<<grid, 256, SMEM_BYTES>>>(x, b_out, out);
}